// round 16
// baseline (speedup 1.0000x reference)
#include <cuda_runtime.h>
#include <cuda_fp16.h>

#define NN 100000
#define EE 1600000
#define HD 32
#define LRELU_S 0.2f
#define PRELU_S 0.1f
#define FULL 0xffffffffu

// ---------------- cp.async helpers ----------------
__device__ __forceinline__ void cp_async16(void* smem_dst, const void* gmem_src) {
    unsigned sa = (unsigned)__cvta_generic_to_shared(smem_dst);
    asm volatile("cp.async.cg.shared.global [%0], [%1], 16;\n" :: "r"(sa), "l"(gmem_src) : "memory");
}
__device__ __forceinline__ void cp_commit() { asm volatile("cp.async.commit_group;\n" ::: "memory"); }
__device__ __forceinline__ void cp_wait0()  { asm volatile("cp.async.wait_group 0;\n" ::: "memory"); }

__device__ __forceinline__ float prelu(float v) { return (v >= 0.f) ? v : PRELU_S * v; }
__device__ __forceinline__ float lrelu(float v) { return (v >= 0.f) ? v : LRELU_S * v; }

// ---------------- static device scratch ----------------
__device__ int    g_deg[2][NN];                 // zero-init; re-zeroed each call in k_fill_t0
__device__ int    g_rank[2][EE];
__device__ int    g_rowptr[2][NN];              // raw per-tile scan output (scan1)
__device__ int    g_rpf[2][NN + 1];             // finalized rowptr (written by fill_t0)
__device__ int    g_csr[2][EE];
__device__ __align__(128) __half g_hh[2][2][NN * HD];   // [buf][graph] fp16 messages (64B rows)
__device__ float  g_al[2][2][NN];
__device__ float  g_ar[2][2][NN];
__device__ __align__(128) float g_se[NN * HD];
__device__ __align__(128) float g_sk[NN * HD];
__device__ __align__(128) __half g_cc[NN][2 * HD];      // fp16 x*[se|sk] (128B rows)
__device__ int    g_part[2][32];

#define SCAN_NB ((NN + 4095) / 4096)

// ---------------- launch 1: degree histogram + edge rank ----------------
__global__ void k_degree(const int* __restrict__ d0, const int* __restrict__ d1) {
    int i = blockIdx.x * blockDim.x + threadIdx.x;
    if (i < EE) {
        g_rank[0][i] = atomicAdd(&g_deg[0][d0[i]], 1);
        g_rank[1][i] = atomicAdd(&g_deg[1][d1[i]], 1);
    }
}

// ---------------- launch 2: per-tile exclusive scan ----------------
__global__ void k_scan1(void) {
    __shared__ int sh[512];
    int graph = blockIdx.y;
    const int* deg = g_deg[graph];
    int* out = g_rowptr[graph];
    int base = blockIdx.x * 4096;
    int tid = threadIdx.x;
    int v[8];
    int s = 0;
#pragma unroll
    for (int k = 0; k < 8; k++) {
        int idx = base + tid * 8 + k;
        v[k] = (idx < NN) ? deg[idx] : 0;
        s += v[k];
    }
    sh[tid] = s;
    __syncthreads();
    for (int off = 1; off < 512; off <<= 1) {
        int t = (tid >= off) ? sh[tid - off] : 0;
        __syncthreads();
        sh[tid] += t;
        __syncthreads();
    }
    if (tid == 511) g_part[graph][blockIdx.x] = sh[511];
    int run = (tid > 0) ? sh[tid - 1] : 0;
#pragma unroll
    for (int k = 0; k < 8; k++) {
        int idx = base + tid * 8 + k;
        if (idx < NN) out[idx] = run;
        run += v[k];
    }
}

// ---------------- launch 3: fill (scan3 fused) + deg re-zero + layer-0 transform ----------------
#define FILL_BLOCKS ((EE + 255) / 256)
#define T0_BLOCKS   ((NN * 32 + 255) / 256)

__global__ void k_fill_t0(const int* __restrict__ s0, const int* __restrict__ d0,
                          const int* __restrict__ s1, const int* __restrict__ d1,
                          const float* __restrict__ x,
                          const float* __restrict__ Ws, const float* __restrict__ a1s, const float* __restrict__ a2s,
                          const float* __restrict__ Wk, const float* __restrict__ a1k, const float* __restrict__ a2k) {
    __shared__ int sPre[2][32];
    if (threadIdx.x < 32) {
        int lane = threadIdx.x;
#pragma unroll
        for (int graph = 0; graph < 2; graph++) {
            int v = (lane < SCAN_NB) ? g_part[graph][lane] : 0;
            int inc = v;
#pragma unroll
            for (int o = 1; o < 32; o <<= 1) {
                int t = __shfl_up_sync(FULL, inc, o);
                if (lane >= o) inc += t;
            }
            sPre[graph][lane] = inc - v;
        }
    }
    __syncthreads();

    if (blockIdx.x < FILL_BLOCKS) {
        int i = blockIdx.x * blockDim.x + threadIdx.x;
        if (i < EE) {
            {
                int d = d0[i];
                g_csr[0][g_rowptr[0][d] + sPre[0][d >> 12] + g_rank[0][i]] = s0[i];
            }
            {
                int d = d1[i];
                g_csr[1][g_rowptr[1][d] + sPre[1][d >> 12] + g_rank[1][i]] = s1[i];
            }
        }
        return;
    }
    int gtid = (blockIdx.x - FILL_BLOCKS) * blockDim.x + threadIdx.x;
    int w = gtid >> 5;
    int lane = threadIdx.x & 31;
    if (w >= NN) return;
    if (lane < 2) {
        g_deg[lane][w] = 0;
        g_rpf[lane][w] = g_rowptr[lane][w] + sPre[lane][w >> 12];
        if (w == 0) g_rpf[lane][NN] = EE;
    }
    float xv = x[w];
    float hs = xv * Ws[lane];
    float hk = xv * Wk[lane];
    g_hh[0][0][w * HD + lane] = __float2half(hs);
    g_hh[0][1][w * HD + lane] = __float2half(hk);
    float r0 = hs * a1s[lane], r1 = hs * a2s[lane];
    float r2 = hk * a1k[lane], r3 = hk * a2k[lane];
#pragma unroll
    for (int o = 16; o; o >>= 1) {
        r0 += __shfl_xor_sync(FULL, r0, o);
        r1 += __shfl_xor_sync(FULL, r1, o);
        r2 += __shfl_xor_sync(FULL, r2, o);
        r3 += __shfl_xor_sync(FULL, r3, o);
    }
    if (lane == 0) {
        g_al[0][0][w] = r0;
        g_ar[0][0][w] = r1;
        g_al[0][1][w] = r2;
        g_ar[0][1][w] = r3;
    }
}

// ---------------- fused GAT agg (both graphs per warp) + SPLIT transform epilogue ----------------
// reg cap: 8 blocks/SM (<=32 regs) to keep 64 warps resident
__global__ void __launch_bounds__(256, 8) k_agg_fused(
        const float* __restrict__ bias0, const float* __restrict__ bias1,
        const float* __restrict__ Ws, const float* __restrict__ a1s, const float* __restrict__ a2s,
        const float* __restrict__ Wk, const float* __restrict__ a1k, const float* __restrict__ a2k,
        const float* __restrict__ x, int buf, int last) {
    __shared__ __half svh[8][32][HD];   // 16KB staging
    __shared__ float sWs[HD * HD];
    __shared__ float sWk[HD * HD];
    // zero staging buffer once: guarantees all rows finite so 0-weight overshoot is safe
    {
        uint4 z = make_uint4(0, 0, 0, 0);
        uint4* sv4 = (uint4*)svh;
#pragma unroll
        for (int i = 0; i < 4; i++) sv4[threadIdx.x + i * 256] = z;
    }
    if (!last) {
        for (int i = threadIdx.x; i < HD * HD; i += 256) {
            sWs[i] = Ws[i];
            sWk[i] = Wk[i];
        }
    }
    __syncthreads();
    int wid = threadIdx.x >> 5;
    int lane = threadIdx.x & 31;
    int n = (blockIdx.x * blockDim.x + threadIdx.x) >> 5;
    if (n >= NN) return;
    int p = lane & 15;
    int hw = lane >> 4;
    int nbuf = buf ^ 1;

    // prefetch both graphs' csr segments
    int start0 = g_rpf[0][n], end0 = g_rpf[0][n + 1];
    int start1 = g_rpf[1][n], end1 = g_rpf[1][n + 1];
    int deg0 = end0 - start0, deg1 = end1 - start1;
    int sc0 = 0, sc1 = 0;
    if (lane < deg0) sc0 = g_csr[0][start0 + lane];
    if (lane < deg1) sc1 = g_csr[1][start1 + lane];

    float2 res[2];
#pragma unroll
    for (int g = 0; g < 2; g++) {
        const __half* __restrict__ hh = g_hh[buf][g];
        const float* __restrict__ al = g_al[buf][g];
        int start = g ? start1 : start0;
        int end   = g ? end1 : end0;
        int deg   = g ? deg1 : deg0;
        int s_c   = g ? sc1 : sc0;
        int cnt = (deg < 32) ? deg : 32;

        // stage 64B rows (predicated): 4 x 16B chunks
        __syncwarp();
        {
            int r4 = lane >> 2;
            int c8 = (lane & 3) * 8;
#pragma unroll
            for (int j = 0; j < 4; j++) {
                int row = j * 8 + r4;
                int s = __shfl_sync(FULL, s_c, row);
                if (row < cnt) cp_async16(&svh[wid][row][c8], &hh[s * HD + c8]);
            }
            cp_commit();
        }

        // softmax weights while staging is in flight (no max shift: logits O(1))
        float arn = g_ar[buf][g][n];
        float p_c = 0.f;
        if (lane < cnt) p_c = __expf(lrelu(al[s_c] + arn));
        float ss = p_c;
#pragma unroll
        for (int o = 16; o; o >>= 1) ss += __shfl_xor_sync(FULL, ss, o);

        cp_wait0();
        __syncwarp();

        // consume: half2, half-warps split rows, predicate-free
        float2 acc = make_float2(0.f, 0.f);
        for (int k = 0; k < cnt; k += 2) {
            int row = k + hw;
            float wgt = __shfl_sync(FULL, p_c, row);
            float2 f = __half22float2(*(const __half2*)&svh[wid][row][2 * p]);
            acc.x += wgt * f.x;
            acc.y += wgt * f.y;
        }
        acc.x += __shfl_xor_sync(FULL, acc.x, 16);
        acc.y += __shfl_xor_sync(FULL, acc.y, 16);

        // rare slow path: degree > 32
        if (deg > 32) {
            float ssl = 0.f;
            for (int i = start + 32; i < end; i++) {
                int s = g_csr[g][i];
                float pw = __expf(lrelu(al[s] + arn));
                ssl += pw;
                float2 f = __half22float2(*(const __half2*)&hh[s * HD + 2 * p]);
                acc.x += pw * f.x;
                acc.y += pw * f.y;
            }
            ss += ssl;
        }

        const float* bias = g ? bias1 : bias0;
        float inv = 1.f / (ss + 1e-16f);
        float2 b2 = *(const float2*)&bias[2 * p];
        float r0 = prelu(acc.x * inv + b2.x);
        float r1 = prelu(acc.y * inv + b2.y);
        res[g] = make_float2(r0, r1);
    }

    if (last) {
        if (lane < 16) {
            *(float2*)&g_se[n * HD + 2 * p] = res[0];
            *(float2*)&g_sk[n * HD + 2 * p] = res[1];
            float xv = x[n];
            *(__half2*)&g_cc[n][2 * p]      = __floats2half2_rn(res[0].x * xv, res[0].y * xv);
            *(__half2*)&g_cc[n][HD + 2 * p] = __floats2half2_rn(res[1].x * xv, res[1].y * xv);
        }
        return;
    }

    // transform epilogue, SPLIT across half-warps: hw0 -> c@Ws (graph 0), hw1 -> c@Wk (graph 1)
    float2 c2 = make_float2(res[0].x + res[1].x, res[0].y + res[1].y);
    const float* __restrict__ M  = hw ? sWk : sWs;
    const float* __restrict__ a1 = hw ? a1k : a1s;
    const float* __restrict__ a2 = hw ? a2k : a2s;
    float2 accM = make_float2(0.f, 0.f);
#pragma unroll
    for (int q = 0; q < 16; q++) {
        float cx = __shfl_sync(FULL, c2.x, q);
        float cy = __shfl_sync(FULL, c2.y, q);
        float2 w0 = *(const float2*)&M[(2 * q) * HD + 2 * p];
        float2 w1 = *(const float2*)&M[(2 * q + 1) * HD + 2 * p];
        accM.x += cx * w0.x + cy * w1.x;
        accM.y += cx * w0.y + cy * w1.y;
    }
    float2 va1 = *(const float2*)&a1[2 * p];
    float2 va2 = *(const float2*)&a2[2 * p];
    float ra = accM.x * va1.x + accM.y * va1.y;
    float rb = accM.x * va2.x + accM.y * va2.y;
#pragma unroll
    for (int o = 8; o; o >>= 1) {
        ra += __shfl_xor_sync(FULL, ra, o);
        rb += __shfl_xor_sync(FULL, rb, o);
    }
    if (p == 0) {
        g_al[nbuf][hw][n] = ra;
        g_ar[nbuf][hw][n] = rb;
    }
    *(__half2*)&g_hh[nbuf][hw][n * HD + 2 * p] = __floats2half2_rn(accM.x, accM.y);
}

// ---------------- final head: 16-row batched staging (16KB) ----------------
__global__ void __launch_bounds__(256) k_final(
                        const float* __restrict__ Wos, const float* __restrict__ bos,
                        const float* __restrict__ Wok, const float* __restrict__ bok,
                        const float* __restrict__ Wd1, const float* __restrict__ bd1,
                        float* __restrict__ out) {
    __shared__ __half svh[8][16][2 * HD];   // 16KB: 16-row batches of packed cc rows
    int wid = threadIdx.x >> 5;
    int lane = threadIdx.x & 31;
    int w = (blockIdx.x * blockDim.x + threadIdx.x) >> 5;
    if (w >= NN) return;

    float2 c2;
    if (lane < 16) c2 = *(const float2*)&g_se[w * HD + 2 * lane];
    else           c2 = *(const float2*)&g_sk[w * HD + 2 * (lane - 16)];

    float4 wos = *(const float4*)&Wos[4 * lane];
    float4 wok = *(const float4*)&Wok[4 * lane];
    float d00 = c2.x * wos.x + c2.y * wos.z;
    float d01 = c2.x * wos.y + c2.y * wos.w;
    float d10 = c2.x * wok.x + c2.y * wok.z;
    float d11 = c2.x * wok.y + c2.y * wok.w;
#pragma unroll
    for (int o = 16; o; o >>= 1) {
        d00 += __shfl_xor_sync(FULL, d00, o);
        d01 += __shfl_xor_sync(FULL, d01, o);
        d10 += __shfl_xor_sync(FULL, d10, o);
        d11 += __shfl_xor_sync(FULL, d11, o);
    }

    int r = lane >> 3;
    int c = (lane & 7) * 8;

    float2 agg[2];
#pragma unroll
    for (int g = 0; g < 2; g++) {
        const int* __restrict__ csr = g_csr[g];
        int st = g_rpf[g][w], en = g_rpf[g][w + 1];
        int deg = en - st;
        int cnt = (deg < 32) ? deg : 32;
        int s_c = 0;
        if (lane < deg) s_c = csr[st + lane];

        __syncwarp();
#pragma unroll
        for (int j = 0; j < 4; j++) {
            int row = j * 4 + r;
            int s = __shfl_sync(FULL, s_c, row);
            if (row < cnt) cp_async16(&svh[wid][row][c], &g_cc[s][c]);
        }
        cp_commit();
        float2 a = make_float2(0.f, 0.f);
        cp_wait0();
        __syncwarp();
        int c0 = (cnt < 16) ? cnt : 16;
        for (int k = 0; k < c0; k++) {
            float2 f = __half22float2(*(const __half2*)&svh[wid][k][2 * lane]);
            a.x += f.x;
            a.y += f.y;
        }
        __syncwarp();
        if (cnt > 16) {
#pragma unroll
            for (int j = 0; j < 4; j++) {
                int row = 16 + j * 4 + r;
                int s = __shfl_sync(FULL, s_c, row);
                if (row < cnt) cp_async16(&svh[wid][row - 16][c], &g_cc[s][c]);
            }
            cp_commit();
            cp_wait0();
            __syncwarp();
            for (int k = 0; k < cnt - 16; k++) {
                float2 f = __half22float2(*(const __half2*)&svh[wid][k][2 * lane]);
                a.x += f.x;
                a.y += f.y;
            }
            __syncwarp();
        }
        for (int i = st + 32; i < en; i++) {
            int s = csr[i];
            float2 f = __half22float2(*(const __half2*)&g_cc[s][2 * lane]);
            a.x += f.x;
            a.y += f.y;
        }
        agg[g] = a;
    }

    float e1sx = fmaxf(agg[0].x + 0.5f * c2.x, 0.f);
    float e1sy = fmaxf(agg[0].y + 0.5f * c2.y, 0.f);
    float e1kx = fmaxf(agg[1].x + 0.5f * c2.x, 0.f);
    float e1ky = fmaxf(agg[1].y + 0.5f * c2.y, 0.f);

    float tx = e1sx + e1kx;
    float ty = e1sy + e1ky;
    float4 wd = *(const float4*)&Wd1[4 * lane];
    float g0 = tx * wd.x + ty * wd.z;
    float g1 = tx * wd.y + ty * wd.w;
#pragma unroll
    for (int o = 16; o; o >>= 1) {
        g0 += __shfl_xor_sync(FULL, g0, o);
        g1 += __shfl_xor_sync(FULL, g1, o);
    }

    if (lane == 0) {
        float s0 = fmaxf(d00 + bos[0], 0.f);
        float s1 = fmaxf(d01 + bos[1], 0.f);
        float k0 = fmaxf(d10 + bok[0], 0.f);
        float k1 = fmaxf(d11 + bok[1], 0.f);
        out[w * 4 + 0] = 0.5f * (s0 + k0);
        out[w * 4 + 1] = 0.5f * (s1 + k1);
        out[w * 4 + 2] = fmaxf(g0 + bd1[0], 0.f);
        out[w * 4 + 3] = fmaxf(g1 + bd1[1], 0.f);
    }
}

// ---------------- launch ----------------
extern "C" void kernel_launch(void* const* d_in, const int* in_sizes, int n_in,
                              void* d_out, int out_size) {
    const float* x        = (const float*)d_in[0];
    const int*   sei      = (const int*)d_in[1];
    const int*   kei      = (const int*)d_in[2];
    const float* W_in_src = (const float*)d_in[3];
    const float* b_in_src = (const float*)d_in[4];
    const float* a1_in_src= (const float*)d_in[5];
    const float* a2_in_src= (const float*)d_in[6];
    const float* W_in_snk = (const float*)d_in[7];
    const float* b_in_snk = (const float*)d_in[8];
    const float* a1_in_snk= (const float*)d_in[9];
    const float* a2_in_snk= (const float*)d_in[10];
    const float* W_src    = (const float*)d_in[11];
    const float* b_src    = (const float*)d_in[12];
    const float* a1_src   = (const float*)d_in[13];
    const float* a2_src   = (const float*)d_in[14];
    const float* W_snk    = (const float*)d_in[15];
    const float* b_snk    = (const float*)d_in[16];
    const float* a1_snk   = (const float*)d_in[17];
    const float* a2_snk   = (const float*)d_in[18];
    const float* W_o_src  = (const float*)d_in[19];
    const float* b_o_src  = (const float*)d_in[20];
    const float* W_o_snk  = (const float*)d_in[21];
    const float* b_o_snk  = (const float*)d_in[22];
    const float* W_d1     = (const float*)d_in[23];
    const float* b_d1     = (const float*)d_in[24];
    float* out = (float*)d_out;

    const int* s0 = sei;
    const int* dd0 = sei + EE;
    const int* s1 = kei;
    const int* dd1 = kei + EE;

    const int TB = 256;

    k_degree<<<(EE + TB - 1) / TB, TB>>>(dd0, dd1);
    {
        dim3 g(SCAN_NB, 2);
        k_scan1<<<g, 512>>>();
    }
    k_fill_t0<<<FILL_BLOCKS + T0_BLOCKS, TB>>>(s0, dd0, s1, dd1, x,
                                               W_in_src, a1_in_src, a2_in_src,
                                               W_in_snk, a1_in_snk, a2_in_snk);

    int node_blocks = (NN * 32 + TB - 1) / TB;

    for (int L = 0; L < 5; L++) {
        const float* bb0 = (L == 0) ? b_in_src : b_src + (L - 1) * HD;
        const float* bb1 = (L == 0) ? b_in_snk : b_snk + (L - 1) * HD;
        int last = (L == 4);
        const float* Ws  = last ? W_src  : W_src  + L * HD * HD;
        const float* Wk  = last ? W_snk  : W_snk  + L * HD * HD;
        const float* a1s = last ? a1_src : a1_src + L * HD;
        const float* a2s = last ? a2_src : a2_src + L * HD;
        const float* a1k = last ? a1_snk : a1_snk + L * HD;
        const float* a2k = last ? a2_snk : a2_snk + L * HD;
        k_agg_fused<<<node_blocks, TB>>>(bb0, bb1, Ws, a1s, a2s, Wk, a1k, a2k,
                                         x, L & 1, last);
    }

    k_final<<<node_blocks, TB>>>(W_o_src, b_o_src, W_o_snk, b_o_snk, W_d1, b_d1, out);
}

// round 17
// speedup vs baseline: 1.2784x; 1.2784x over previous
#include <cuda_runtime.h>
#include <cuda_fp16.h>

#define NN 100000
#define EE 1600000
#define HD 32
#define LRELU_S 0.2f
#define PRELU_S 0.1f
#define FULL 0xffffffffu

// ---------------- cp.async helpers ----------------
__device__ __forceinline__ void cp_async16(void* smem_dst, const void* gmem_src) {
    unsigned sa = (unsigned)__cvta_generic_to_shared(smem_dst);
    asm volatile("cp.async.cg.shared.global [%0], [%1], 16;\n" :: "r"(sa), "l"(gmem_src) : "memory");
}
__device__ __forceinline__ void cp_commit() { asm volatile("cp.async.commit_group;\n" ::: "memory"); }
__device__ __forceinline__ void cp_wait0()  { asm volatile("cp.async.wait_group 0;\n" ::: "memory"); }

__device__ __forceinline__ float prelu(float v) { return (v >= 0.f) ? v : PRELU_S * v; }
__device__ __forceinline__ float lrelu(float v) { return (v >= 0.f) ? v : LRELU_S * v; }
__device__ __forceinline__ unsigned packh2(__half a, __half b) {
    __half2 h = __halves2half2(a, b);
    return *(unsigned*)&h;
}

// ---------------- static device scratch ----------------
__device__ int    g_deg[2][NN];
__device__ int    g_rank[2][EE];
__device__ int    g_rowptr[2][NN];
__device__ int    g_rpf[2][NN + 1];
__device__ int    g_csr[2][EE];
__device__ __align__(128) __half g_hh[2][2][NN * HD];   // [buf][graph] fp16 messages
__device__ float  g_al[2][2][NN];
__device__ float  g_ar[2][2][NN];
__device__ __align__(128) __half g_ch[NN][HD];          // fp16 c = se+sk (GEMM input)
__device__ __align__(128) float g_se[NN * HD];
__device__ __align__(128) float g_sk[NN * HD];
__device__ __align__(128) __half g_cc[NN][2 * HD];      // fp16 x*[se|sk]
__device__ int    g_part[2][32];

#define SCAN_NB ((NN + 4095) / 4096)

// ---------------- launch 1: degree histogram + edge rank ----------------
__global__ void k_degree(const int* __restrict__ d0, const int* __restrict__ d1) {
    int i = blockIdx.x * blockDim.x + threadIdx.x;
    if (i < EE) {
        g_rank[0][i] = atomicAdd(&g_deg[0][d0[i]], 1);
        g_rank[1][i] = atomicAdd(&g_deg[1][d1[i]], 1);
    }
}

// ---------------- launch 2: per-tile exclusive scan ----------------
__global__ void k_scan1(void) {
    __shared__ int sh[512];
    int graph = blockIdx.y;
    const int* deg = g_deg[graph];
    int* out = g_rowptr[graph];
    int base = blockIdx.x * 4096;
    int tid = threadIdx.x;
    int v[8];
    int s = 0;
#pragma unroll
    for (int k = 0; k < 8; k++) {
        int idx = base + tid * 8 + k;
        v[k] = (idx < NN) ? deg[idx] : 0;
        s += v[k];
    }
    sh[tid] = s;
    __syncthreads();
    for (int off = 1; off < 512; off <<= 1) {
        int t = (tid >= off) ? sh[tid - off] : 0;
        __syncthreads();
        sh[tid] += t;
        __syncthreads();
    }
    if (tid == 511) g_part[graph][blockIdx.x] = sh[511];
    int run = (tid > 0) ? sh[tid - 1] : 0;
#pragma unroll
    for (int k = 0; k < 8; k++) {
        int idx = base + tid * 8 + k;
        if (idx < NN) out[idx] = run;
        run += v[k];
    }
}

// ---------------- launch 3: fill + deg re-zero + layer-0 transform ----------------
#define FILL_BLOCKS ((EE + 255) / 256)
#define T0_BLOCKS   ((NN * 32 + 255) / 256)

__global__ void k_fill_t0(const int* __restrict__ s0, const int* __restrict__ d0,
                          const int* __restrict__ s1, const int* __restrict__ d1,
                          const float* __restrict__ x,
                          const float* __restrict__ Ws, const float* __restrict__ a1s, const float* __restrict__ a2s,
                          const float* __restrict__ Wk, const float* __restrict__ a1k, const float* __restrict__ a2k) {
    __shared__ int sPre[2][32];
    if (threadIdx.x < 32) {
        int lane = threadIdx.x;
#pragma unroll
        for (int graph = 0; graph < 2; graph++) {
            int v = (lane < SCAN_NB) ? g_part[graph][lane] : 0;
            int inc = v;
#pragma unroll
            for (int o = 1; o < 32; o <<= 1) {
                int t = __shfl_up_sync(FULL, inc, o);
                if (lane >= o) inc += t;
            }
            sPre[graph][lane] = inc - v;
        }
    }
    __syncthreads();

    if (blockIdx.x < FILL_BLOCKS) {
        int i = blockIdx.x * blockDim.x + threadIdx.x;
        if (i < EE) {
            {
                int d = d0[i];
                g_csr[0][g_rowptr[0][d] + sPre[0][d >> 12] + g_rank[0][i]] = s0[i];
            }
            {
                int d = d1[i];
                g_csr[1][g_rowptr[1][d] + sPre[1][d >> 12] + g_rank[1][i]] = s1[i];
            }
        }
        return;
    }
    int gtid = (blockIdx.x - FILL_BLOCKS) * blockDim.x + threadIdx.x;
    int w = gtid >> 5;
    int lane = threadIdx.x & 31;
    if (w >= NN) return;
    if (lane < 2) {
        g_deg[lane][w] = 0;
        g_rpf[lane][w] = g_rowptr[lane][w] + sPre[lane][w >> 12];
        if (w == 0) g_rpf[lane][NN] = EE;
    }
    float xv = x[w];
    float hs = xv * Ws[lane];
    float hk = xv * Wk[lane];
    g_hh[0][0][w * HD + lane] = __float2half(hs);
    g_hh[0][1][w * HD + lane] = __float2half(hk);
    float r0 = hs * a1s[lane], r1 = hs * a2s[lane];
    float r2 = hk * a1k[lane], r3 = hk * a2k[lane];
#pragma unroll
    for (int o = 16; o; o >>= 1) {
        r0 += __shfl_xor_sync(FULL, r0, o);
        r1 += __shfl_xor_sync(FULL, r1, o);
        r2 += __shfl_xor_sync(FULL, r2, o);
        r3 += __shfl_xor_sync(FULL, r3, o);
    }
    if (lane == 0) {
        g_al[0][0][w] = r0;
        g_ar[0][0][w] = r1;
        g_al[0][1][w] = r2;
        g_ar[0][1][w] = r3;
    }
}

// ---------------- fused GAT agg (both graphs per warp), NO transform epilogue ----------------
__global__ void __launch_bounds__(256) k_agg_fused(
        const float* __restrict__ bias0, const float* __restrict__ bias1,
        const float* __restrict__ x, int buf, int last) {
    __shared__ __half svh[8][32][HD];   // 16KB staging
    // zero staging once: rows finite -> 0-weight overshoot safe
    {
        uint4 z = make_uint4(0, 0, 0, 0);
        uint4* sv4 = (uint4*)svh;
#pragma unroll
        for (int i = 0; i < 4; i++) sv4[threadIdx.x + i * 256] = z;
    }
    __syncthreads();
    int wid = threadIdx.x >> 5;
    int lane = threadIdx.x & 31;
    int n = (blockIdx.x * blockDim.x + threadIdx.x) >> 5;
    if (n >= NN) return;
    int p = lane & 15;
    int hw = lane >> 4;

    int start0 = g_rpf[0][n], end0 = g_rpf[0][n + 1];
    int start1 = g_rpf[1][n], end1 = g_rpf[1][n + 1];
    int deg0 = end0 - start0, deg1 = end1 - start1;
    int sc0 = 0, sc1 = 0;
    if (lane < deg0) sc0 = g_csr[0][start0 + lane];
    if (lane < deg1) sc1 = g_csr[1][start1 + lane];

    float2 res[2];
#pragma unroll
    for (int g = 0; g < 2; g++) {
        const __half* __restrict__ hh = g_hh[buf][g];
        const float* __restrict__ al = g_al[buf][g];
        int start = g ? start1 : start0;
        int end   = g ? end1 : end0;
        int deg   = g ? deg1 : deg0;
        int s_c   = g ? sc1 : sc0;
        int cnt = (deg < 32) ? deg : 32;

        __syncwarp();
        {
            int r4 = lane >> 2;
            int c8 = (lane & 3) * 8;
#pragma unroll
            for (int j = 0; j < 4; j++) {
                int row = j * 8 + r4;
                int s = __shfl_sync(FULL, s_c, row);
                if (row < cnt) cp_async16(&svh[wid][row][c8], &hh[s * HD + c8]);
            }
            cp_commit();
        }

        float arn = g_ar[buf][g][n];
        float p_c = 0.f;
        if (lane < cnt) p_c = __expf(lrelu(al[s_c] + arn));
        float ss = p_c;
#pragma unroll
        for (int o = 16; o; o >>= 1) ss += __shfl_xor_sync(FULL, ss, o);

        cp_wait0();
        __syncwarp();

        float2 acc = make_float2(0.f, 0.f);
        for (int k = 0; k < cnt; k += 2) {
            int row = k + hw;
            float wgt = __shfl_sync(FULL, p_c, row);
            float2 f = __half22float2(*(const __half2*)&svh[wid][row][2 * p]);
            acc.x += wgt * f.x;
            acc.y += wgt * f.y;
        }
        acc.x += __shfl_xor_sync(FULL, acc.x, 16);
        acc.y += __shfl_xor_sync(FULL, acc.y, 16);

        if (deg > 32) {
            float ssl = 0.f;
            for (int i = start + 32; i < end; i++) {
                int s = g_csr[g][i];
                float pw = __expf(lrelu(al[s] + arn));
                ssl += pw;
                float2 f = __half22float2(*(const __half2*)&hh[s * HD + 2 * p]);
                acc.x += pw * f.x;
                acc.y += pw * f.y;
            }
            ss += ssl;
        }

        const float* bias = g ? bias1 : bias0;
        float inv = 1.f / (ss + 1e-16f);
        float2 b2 = *(const float2*)&bias[2 * p];
        float r0 = prelu(acc.x * inv + b2.x);
        float r1 = prelu(acc.y * inv + b2.y);
        res[g] = make_float2(r0, r1);
    }

    if (last) {
        if (lane < 16) {
            *(float2*)&g_se[n * HD + 2 * p] = res[0];
            *(float2*)&g_sk[n * HD + 2 * p] = res[1];
            float xv = x[n];
            *(__half2*)&g_cc[n][2 * p]      = __floats2half2_rn(res[0].x * xv, res[0].y * xv);
            *(__half2*)&g_cc[n][HD + 2 * p] = __floats2half2_rn(res[1].x * xv, res[1].y * xv);
        }
    } else {
        if (lane < 16) {
            *(__half2*)&g_ch[n][2 * p] = __floats2half2_rn(res[0].x + res[1].x, res[0].y + res[1].y);
        }
    }
}

// ---------------- transform via tensor cores: [NN x 32] @ [Ws|Wk|dots] ----------------
// One 16-node tile per warp. A = c rows (fp16, direct LDG), B from smem fp16 W.
#define TM_TILES ((NN + 15) / 16)          // 6250
#define TM_BLOCKS ((TM_TILES + 7) / 8)     // 782

__global__ void __launch_bounds__(256) k_tmma(
        const float* __restrict__ Ws, const float* __restrict__ Wk,
        const float* __restrict__ a1s, const float* __restrict__ a2s,
        const float* __restrict__ a1k, const float* __restrict__ a2k,
        int nbuf) {
    __shared__ __half sW[32][80];   // cols 0-31 Ws, 32-63 Wk, 64-67 dot cols, 68-71 zero
    int tid = threadIdx.x;
    for (int i = tid; i < 32 * 32; i += 256) {
        int r = i >> 5, cc = i & 31;
        sW[r][cc]      = __float2half(Ws[i]);
        sW[r][32 + cc] = __float2half(Wk[i]);
    }
    if (tid < 32) {
        float d0 = 0.f, d1 = 0.f, d2 = 0.f, d3 = 0.f;
        for (int m = 0; m < 32; m++) {
            float ws = Ws[tid * 32 + m], wk = Wk[tid * 32 + m];
            d0 += ws * a1s[m];
            d1 += ws * a2s[m];
            d2 += wk * a1k[m];
            d3 += wk * a2k[m];
        }
        sW[tid][64] = __float2half(d0);
        sW[tid][65] = __float2half(d1);
        sW[tid][66] = __float2half(d2);
        sW[tid][67] = __float2half(d3);
        sW[tid][68] = __float2half(0.f);
        sW[tid][69] = __float2half(0.f);
        sW[tid][70] = __float2half(0.f);
        sW[tid][71] = __float2half(0.f);
    }
    __syncthreads();

    int warp = tid >> 5, lane = tid & 31;
    int g = lane >> 2, t = lane & 3;
    int tile = blockIdx.x * 8 + warp;
    if (tile >= TM_TILES) return;
    int row0 = tile * 16 + g;
    int row8 = row0 + 8;

    // A fragments (hoisted, both k-steps): direct LDG.32 from fp16 c rows
    const unsigned* C0 = (const unsigned*)&g_ch[row0][0];   // 16 uints per row
    const unsigned* C8 = (const unsigned*)&g_ch[row8][0];
    unsigned a00 = C0[t],     a01 = C8[t],     a02 = C0[t + 4],  a03 = C8[t + 4];   // k 0-15
    unsigned a10 = C0[t + 8], a11 = C8[t + 8], a12 = C0[t + 12], a13 = C8[t + 12];  // k 16-31

    __half* __restrict__ h0 = g_hh[nbuf][0];
    __half* __restrict__ h1 = g_hh[nbuf][1];

#pragma unroll
    for (int b = 0; b < 9; b++) {
        int col = b * 8 + g;
        unsigned b00 = packh2(sW[2 * t][col],      sW[2 * t + 1][col]);
        unsigned b01 = packh2(sW[2 * t + 8][col],  sW[2 * t + 9][col]);
        unsigned b10 = packh2(sW[16 + 2 * t][col], sW[17 + 2 * t][col]);
        unsigned b11 = packh2(sW[24 + 2 * t][col], sW[25 + 2 * t][col]);
        float d0 = 0.f, d1 = 0.f, d2 = 0.f, d3 = 0.f;
        asm volatile(
            "mma.sync.aligned.m16n8k16.row.col.f32.f16.f16.f32 "
            "{%0,%1,%2,%3}, {%4,%5,%6,%7}, {%8,%9}, {%0,%1,%2,%3};"
            : "+f"(d0), "+f"(d1), "+f"(d2), "+f"(d3)
            : "r"(a00), "r"(a01), "r"(a02), "r"(a03), "r"(b00), "r"(b01));
        asm volatile(
            "mma.sync.aligned.m16n8k16.row.col.f32.f16.f16.f32 "
            "{%0,%1,%2,%3}, {%4,%5,%6,%7}, {%8,%9}, {%0,%1,%2,%3};"
            : "+f"(d0), "+f"(d1), "+f"(d2), "+f"(d3)
            : "r"(a10), "r"(a11), "r"(a12), "r"(a13), "r"(b10), "r"(b11));
        if (b < 8) {
            int gph = b >> 2;
            int cb = (b & 3) * 8 + 2 * t;
            __half* dst = gph ? h1 : h0;
            *(__half2*)&dst[row0 * HD + cb] = __floats2half2_rn(d0, d1);
            *(__half2*)&dst[row8 * HD + cb] = __floats2half2_rn(d2, d3);
        } else {
            if (t == 0) {
                g_al[nbuf][0][row0] = d0;
                g_ar[nbuf][0][row0] = d1;
                g_al[nbuf][0][row8] = d2;
                g_ar[nbuf][0][row8] = d3;
            } else if (t == 1) {
                g_al[nbuf][1][row0] = d0;
                g_ar[nbuf][1][row0] = d1;
                g_al[nbuf][1][row8] = d2;
                g_ar[nbuf][1][row8] = d3;
            }
        }
    }
}

// ---------------- final head (unchanged from R15) ----------------
__global__ void __launch_bounds__(256) k_final(
                        const float* __restrict__ Wos, const float* __restrict__ bos,
                        const float* __restrict__ Wok, const float* __restrict__ bok,
                        const float* __restrict__ Wd1, const float* __restrict__ bd1,
                        float* __restrict__ out) {
    __shared__ __half svh[8][16][2 * HD];
    int wid = threadIdx.x >> 5;
    int lane = threadIdx.x & 31;
    int w = (blockIdx.x * blockDim.x + threadIdx.x) >> 5;
    if (w >= NN) return;

    float2 c2;
    if (lane < 16) c2 = *(const float2*)&g_se[w * HD + 2 * lane];
    else           c2 = *(const float2*)&g_sk[w * HD + 2 * (lane - 16)];

    float4 wos = *(const float4*)&Wos[4 * lane];
    float4 wok = *(const float4*)&Wok[4 * lane];
    float d00 = c2.x * wos.x + c2.y * wos.z;
    float d01 = c2.x * wos.y + c2.y * wos.w;
    float d10 = c2.x * wok.x + c2.y * wok.z;
    float d11 = c2.x * wok.y + c2.y * wok.w;
#pragma unroll
    for (int o = 16; o; o >>= 1) {
        d00 += __shfl_xor_sync(FULL, d00, o);
        d01 += __shfl_xor_sync(FULL, d01, o);
        d10 += __shfl_xor_sync(FULL, d10, o);
        d11 += __shfl_xor_sync(FULL, d11, o);
    }

    int r = lane >> 3;
    int c = (lane & 7) * 8;

    float2 agg[2];
#pragma unroll
    for (int g = 0; g < 2; g++) {
        const int* __restrict__ csr = g_csr[g];
        int st = g_rpf[g][w], en = g_rpf[g][w + 1];
        int deg = en - st;
        int cnt = (deg < 32) ? deg : 32;
        int s_c = 0;
        if (lane < deg) s_c = csr[st + lane];

        __syncwarp();
#pragma unroll
        for (int j = 0; j < 4; j++) {
            int row = j * 4 + r;
            int s = __shfl_sync(FULL, s_c, row);
            if (row < cnt) cp_async16(&svh[wid][row][c], &g_cc[s][c]);
        }
        cp_commit();
        float2 a = make_float2(0.f, 0.f);
        cp_wait0();
        __syncwarp();
        int c0 = (cnt < 16) ? cnt : 16;
        for (int k = 0; k < c0; k++) {
            float2 f = __half22float2(*(const __half2*)&svh[wid][k][2 * lane]);
            a.x += f.x;
            a.y += f.y;
        }
        __syncwarp();
        if (cnt > 16) {
#pragma unroll
            for (int j = 0; j < 4; j++) {
                int row = 16 + j * 4 + r;
                int s = __shfl_sync(FULL, s_c, row);
                if (row < cnt) cp_async16(&svh[wid][row - 16][c], &g_cc[s][c]);
            }
            cp_commit();
            cp_wait0();
            __syncwarp();
            for (int k = 0; k < cnt - 16; k++) {
                float2 f = __half22float2(*(const __half2*)&svh[wid][k][2 * lane]);
                a.x += f.x;
                a.y += f.y;
            }
            __syncwarp();
        }
        for (int i = st + 32; i < en; i++) {
            int s = csr[i];
            float2 f = __half22float2(*(const __half2*)&g_cc[s][2 * lane]);
            a.x += f.x;
            a.y += f.y;
        }
        agg[g] = a;
    }

    float e1sx = fmaxf(agg[0].x + 0.5f * c2.x, 0.f);
    float e1sy = fmaxf(agg[0].y + 0.5f * c2.y, 0.f);
    float e1kx = fmaxf(agg[1].x + 0.5f * c2.x, 0.f);
    float e1ky = fmaxf(agg[1].y + 0.5f * c2.y, 0.f);

    float tx = e1sx + e1kx;
    float ty = e1sy + e1ky;
    float4 wd = *(const float4*)&Wd1[4 * lane];
    float g0 = tx * wd.x + ty * wd.z;
    float g1 = tx * wd.y + ty * wd.w;
#pragma unroll
    for (int o = 16; o; o >>= 1) {
        g0 += __shfl_xor_sync(FULL, g0, o);
        g1 += __shfl_xor_sync(FULL, g1, o);
    }

    if (lane == 0) {
        float s0 = fmaxf(d00 + bos[0], 0.f);
        float s1 = fmaxf(d01 + bos[1], 0.f);
        float k0 = fmaxf(d10 + bok[0], 0.f);
        float k1 = fmaxf(d11 + bok[1], 0.f);
        out[w * 4 + 0] = 0.5f * (s0 + k0);
        out[w * 4 + 1] = 0.5f * (s1 + k1);
        out[w * 4 + 2] = fmaxf(g0 + bd1[0], 0.f);
        out[w * 4 + 3] = fmaxf(g1 + bd1[1], 0.f);
    }
}

// ---------------- launch ----------------
extern "C" void kernel_launch(void* const* d_in, const int* in_sizes, int n_in,
                              void* d_out, int out_size) {
    const float* x        = (const float*)d_in[0];
    const int*   sei      = (const int*)d_in[1];
    const int*   kei      = (const int*)d_in[2];
    const float* W_in_src = (const float*)d_in[3];
    const float* b_in_src = (const float*)d_in[4];
    const float* a1_in_src= (const float*)d_in[5];
    const float* a2_in_src= (const float*)d_in[6];
    const float* W_in_snk = (const float*)d_in[7];
    const float* b_in_snk = (const float*)d_in[8];
    const float* a1_in_snk= (const float*)d_in[9];
    const float* a2_in_snk= (const float*)d_in[10];
    const float* W_src    = (const float*)d_in[11];
    const float* b_src    = (const float*)d_in[12];
    const float* a1_src   = (const float*)d_in[13];
    const float* a2_src   = (const float*)d_in[14];
    const float* W_snk    = (const float*)d_in[15];
    const float* b_snk    = (const float*)d_in[16];
    const float* a1_snk   = (const float*)d_in[17];
    const float* a2_snk   = (const float*)d_in[18];
    const float* W_o_src  = (const float*)d_in[19];
    const float* b_o_src  = (const float*)d_in[20];
    const float* W_o_snk  = (const float*)d_in[21];
    const float* b_o_snk  = (const float*)d_in[22];
    const float* W_d1     = (const float*)d_in[23];
    const float* b_d1     = (const float*)d_in[24];
    float* out = (float*)d_out;

    const int* s0 = sei;
    const int* dd0 = sei + EE;
    const int* s1 = kei;
    const int* dd1 = kei + EE;

    const int TB = 256;

    k_degree<<<(EE + TB - 1) / TB, TB>>>(dd0, dd1);
    {
        dim3 g(SCAN_NB, 2);
        k_scan1<<<g, 512>>>();
    }
    k_fill_t0<<<FILL_BLOCKS + T0_BLOCKS, TB>>>(s0, dd0, s1, dd1, x,
                                               W_in_src, a1_in_src, a2_in_src,
                                               W_in_snk, a1_in_snk, a2_in_snk);

    int node_blocks = (NN * 32 + TB - 1) / TB;

    for (int L = 0; L < 5; L++) {
        const float* bb0 = (L == 0) ? b_in_src : b_src + (L - 1) * HD;
        const float* bb1 = (L == 0) ? b_in_snk : b_snk + (L - 1) * HD;
        int last = (L == 4);
        k_agg_fused<<<node_blocks, TB>>>(bb0, bb1, x, L & 1, last);
        if (!last) {
            k_tmma<<<TM_BLOCKS, TB>>>(W_src + L * HD * HD, W_snk + L * HD * HD,
                                      a1_src + L * HD, a2_src + L * HD,
                                      a1_snk + L * HD, a2_snk + L * HD,
                                      (L & 1) ^ 1);
        }
    }

    k_final<<<node_blocks, TB>>>(W_o_src, b_o_src, W_o_snk, b_o_snk, W_d1, b_d1, out);
}